// round 14
// baseline (speedup 1.0000x reference)
#include <cuda_runtime.h>
#include <cstdint>

// ---------------- problem constants ----------------
#define BATCH    16
#define TSEQ     16384
#define CIN      8
#define GRANGES  256         // ranges per batch
#define LSTEPS   64          // TSEQ / GRANGES, multiple of CHUNK=32
#define SIGLEN   819         // 9 + 81 + 729
#define HID      256
#define SUBT     16          // subtrees per batch
#define RPS      16          // ranges per subtree (RPS*SUBT == GRANGES)
#define TSTRIDE  68          // channel-major row stride (floats): 16B-aligned, bank-spread

// ---------------- scratch (no allocations allowed) ----------------
__device__ float  g_part[BATCH * GRANGES * SIGLEN];     // fp32 range signatures
__device__ float2 g_sub [BATCH * SUBT    * SIGLEN];     // df64 subtree signatures
__device__ float  g_flat[BATCH * SIGLEN];               // log-signature features

// ---------------- float-float (df64) helpers --------------------------
struct df2 { float hi, lo; };

__device__ __forceinline__ df2 df_add(df2 a, float b) {
    float s = __fadd_rn(a.hi, b);
    float v = __fsub_rn(s, a.hi);
    float e = __fadd_rn(__fsub_rn(a.hi, __fsub_rn(s, v)), __fsub_rn(b, v));
    e = __fadd_rn(e, a.lo);
    float hi = __fadd_rn(s, e);
    float lo = __fsub_rn(e, __fsub_rn(hi, s));
    df2 r; r.hi = hi; r.lo = lo; return r;
}

__device__ __forceinline__ df2 df_add2(df2 a, df2 b) {
    float s = __fadd_rn(a.hi, b.hi);
    float v = __fsub_rn(s, a.hi);
    float e = __fadd_rn(__fsub_rn(a.hi, __fsub_rn(s, v)), __fsub_rn(b.hi, v));
    e = __fadd_rn(e, __fadd_rn(a.lo, b.lo));
    float hi = __fadd_rn(s, e);
    float lo = __fsub_rn(e, __fsub_rn(hi, s));
    df2 r; r.hi = hi; r.lo = lo; return r;
}

__device__ __forceinline__ df2 df_fmaf(df2 a, df2 p, float q) {
    // a += p*q  (p df64, q fp32)
    float ph = __fmul_rn(p.hi, q);
    float pl = __fmaf_rn(p.hi, q, -ph);
    pl = __fmaf_rn(p.lo, q, pl);
    df2 r = df_add(a, ph);
    r.lo = __fadd_rn(r.lo, pl);
    float hi = __fadd_rn(r.hi, r.lo);
    r.lo = __fsub_rn(r.lo, __fsub_rn(hi, r.hi));
    r.hi = hi;
    return r;
}

__device__ __forceinline__ df2 df_fmaf2(df2 a, df2 p, df2 q) {
    // a += p*q  (both df64)
    float ph = __fmul_rn(p.hi, q.hi);
    float pl = __fmaf_rn(p.hi, q.hi, -ph);
    pl = __fmaf_rn(p.hi, q.lo, pl);
    pl = __fmaf_rn(p.lo, q.hi, pl);
    df2 r = df_add(a, ph);
    r.lo = __fadd_rn(r.lo, pl);
    float hi = __fadd_rn(r.hi, r.lo);
    r.lo = __fsub_rn(r.lo, __fsub_rn(hi, r.hi));
    r.hi = hi;
    return r;
}

// =====================================================================
// Kernel 1: per-range truncated signature (levels 1..3), fp32.
// (identical to R11/R12 — 27.1/27.5 us measured)
// =====================================================================
__global__ __launch_bounds__(96)
void sig_partial_kernel(const float* __restrict__ x)
{
    __shared__ __align__(16) float ds [LSTEPS * 8];
    __shared__ __align__(16) float dst[8 * TSTRIDE];

    const int b = blockIdx.y;
    const int g = blockIdx.x;
    const int tid = threadIdx.x;
    const float DT = 1.0f / 32.0f;

    const long base = ((long)b * TSEQ + (long)g * LSTEPS) * CIN;
    for (int idx = tid; idx < LSTEPS * 8; idx += 96) {
        int s = idx >> 3, c = idx & 7;
        float cur  = x[base + idx];
        float prev = (s & 31) ? x[base + idx - 8] : 0.0f;
        ds[idx] = cur - prev;
        dst[c * TSTRIDE + s] = cur - prev;
    }
    __syncthreads();

    if (tid < 81) {
        const int i = tid / 9;
        const int j = tid % 9;
        float s1i = 0.0f, s2 = 0.0f;
        uint64_t s3p[4];
        #pragma unroll
        for (int k = 0; k < 4; ++k) s3p[k] = 0ull;
        float s38 = 0.0f;
        const float4 DT4 = make_float4(DT, DT, DT, DT);

        #pragma unroll 1
        for (int s0 = 0; s0 < LSTEPS; s0 += 4) {
            float4 di4 = (i < 8) ? *reinterpret_cast<const float4*>(&dst[i * TSTRIDE + s0]) : DT4;
            float4 dj4 = (j < 8) ? *reinterpret_cast<const float4*>(&dst[j * TSTRIDE + s0]) : DT4;
            const float* dp = ds + s0 * 8;

            #pragma unroll
            for (int u = 0; u < 4; ++u, dp += 8) {
                float di = (u == 0) ? di4.x : (u == 1) ? di4.y : (u == 2) ? di4.z : di4.w;
                float dj = (u == 0) ? dj4.x : (u == 1) ? dj4.y : (u == 2) ? dj4.z : dj4.w;
                const ulonglong2* q = reinterpret_cast<const ulonglong2*>(dp);
                ulonglong2 dl = q[0];
                ulonglong2 dh = q[1];

                float a = fmaf(fmaf(di, (1.0f / 3.0f), s1i), 0.5f * dj, s2);
                uint64_t ap;
                asm("mov.b64 %0, {%1, %2};" : "=l"(ap) : "f"(a), "f"(a));
                asm("fma.rn.f32x2 %0, %1, %2, %3;" : "=l"(s3p[0]) : "l"(ap), "l"(dl.x), "l"(s3p[0]));
                asm("fma.rn.f32x2 %0, %1, %2, %3;" : "=l"(s3p[1]) : "l"(ap), "l"(dl.y), "l"(s3p[1]));
                asm("fma.rn.f32x2 %0, %1, %2, %3;" : "=l"(s3p[2]) : "l"(ap), "l"(dh.x), "l"(s3p[2]));
                asm("fma.rn.f32x2 %0, %1, %2, %3;" : "=l"(s3p[3]) : "l"(ap), "l"(dh.y), "l"(s3p[3]));
                s38 = fmaf(a, DT, s38);

                s2  = fmaf(fmaf(di, 0.5f, s1i), dj, s2);
                s1i += di;
            }
        }

        float* out = g_part + (long)(b * GRANGES + g) * SIGLEN;
        if (j == 0) out[i] = s1i;
        out[9 + tid] = s2;
        float* o3 = out + 90 + tid * 9;
        #pragma unroll
        for (int k = 0; k < 4; ++k) {
            float lo, hi;
            asm("mov.b64 {%0, %1}, %2;" : "=f"(lo), "=f"(hi) : "l"(s3p[k]));
            o3[2 * k]     = lo;
            o3[2 * k + 1] = hi;
        }
        o3[8] = s38;
    }
}

// =====================================================================
// Launch A: fold RPS fp32 range sigs -> one df64 subtree sig.
// Operands register-batched upfront; level-3 acc in regs; levels 1+2 in
// shared ping-pong. Grid (SUBT, BATCH), 768 threads (729 active).
// =====================================================================
__global__ __launch_bounds__(768)
void combine_kernel()
{
    __shared__ float s1h[2][9],  s1l[2][9];
    __shared__ float s2h[2][81], s2l[2][81];

    const int b = blockIdx.y;
    const int sx = blockIdx.x;
    const int t = threadIdx.x;
    const bool act = t < 729;
    const int i = t / 81;
    const int j = (t / 9) % 9;
    const int k = t % 9;

    const float* base = g_part + (long)(b * GRANGES + sx * RPS) * SIGLEN;

    df2 c3 = { 0.f, 0.f };
    float ob1[RPS - 1], ob2[RPS - 1], ob3[RPS - 1];
    if (act) {
        c3.hi = base[90 + t];
        if (t < 81) { s2h[0][t] = base[9 + t]; s2l[0][t] = 0.f; }
        if (t < 9)  { s1h[0][t] = base[t];     s1l[0][t] = 0.f; }
        #pragma unroll
        for (int p = 1; p < RPS; ++p) {
            const float* B = base + (long)p * SIGLEN;
            ob1[p - 1] = B[k];
            ob2[p - 1] = B[9 + j * 9 + k];
            ob3[p - 1] = B[90 + t];
        }
    }
    __syncthreads();

    int cur = 0;
    #pragma unroll
    for (int p = 1; p < RPS; ++p) {
        if (act) {
            float b1k = ob1[p - 1], b2jk = ob2[p - 1], b3 = ob3[p - 1];
            df2 a1i  = { s1h[cur][i],         s1l[cur][i] };
            df2 a2ij = { s2h[cur][i * 9 + j], s2l[cur][i * 9 + j] };
            c3 = df_add(c3, b3);
            c3 = df_fmaf(c3, a1i, b2jk);
            c3 = df_fmaf(c3, a2ij, b1k);
            if (t < 81) {
                df2 a1s = { s1h[cur][t / 9], s1l[cur][t / 9] };
                df2 c2  = { s2h[cur][t],     s2l[cur][t] };
                c2 = df_add(c2, b2jk);
                c2 = df_fmaf(c2, a1s, b1k);
                s2h[cur ^ 1][t] = c2.hi;  s2l[cur ^ 1][t] = c2.lo;
            }
            if (t < 9) {
                df2 c1 = { s1h[cur][t], s1l[cur][t] };
                c1 = df_add(c1, b1k);
                s1h[cur ^ 1][t] = c1.hi;  s1l[cur ^ 1][t] = c1.lo;
            }
        }
        __syncthreads();
        cur ^= 1;
    }

    float2* out = g_sub + (long)(b * SUBT + sx) * SIGLEN;
    if (act) {
        out[90 + t] = make_float2(c3.hi, c3.lo);
        if (t < 81) out[9 + t] = make_float2(s2h[cur][t], s2l[cur][t]);
        if (t < 9)  out[t]     = make_float2(s1h[cur][t], s1l[cur][t]);
    }
}

// =====================================================================
// Launch B1: fold SUBT df64 subtree sigs, fp64 log3, write flat to
// global; initialize out[b] = b2. Grid BATCH, 768 threads.
// =====================================================================
#define NB1 8
#define NB2 (SUBT - 1 - NB1)

__global__ __launch_bounds__(768)
void finalfold_kernel(const float* __restrict__ b2v, float* __restrict__ out)
{
    __shared__ float s1h[2][9],  s1l[2][9];
    __shared__ float s2h[2][81], s2l[2][81];

    const int b = blockIdx.x;
    const int t = threadIdx.x;
    const bool act = t < 729;
    const int i = t / 81;
    const int j = (t / 9) % 9;
    const int k = t % 9;

    const float2* sub = g_sub + (long)(b * SUBT) * SIGLEN;

    df2 c3 = { 0.f, 0.f };
    float2 ob1[NB1], ob2[NB1], ob3[NB1];
    if (act) {
        { float2 v = sub[90 + t]; c3.hi = v.x; c3.lo = v.y; }
        if (t < 81) { float2 v = sub[9 + t]; s2h[0][t] = v.x; s2l[0][t] = v.y; }
        if (t < 9)  { float2 v = sub[t];     s1h[0][t] = v.x; s1l[0][t] = v.y; }
        #pragma unroll
        for (int p = 1; p <= NB1; ++p) {
            const float2* B = sub + (long)p * SIGLEN;
            ob1[p - 1] = B[k];
            ob2[p - 1] = B[9 + j * 9 + k];
            ob3[p - 1] = B[90 + t];
        }
    }
    __syncthreads();

    int cur = 0;
    #pragma unroll
    for (int p = 1; p <= NB1; ++p) {
        if (act) {
            df2 b1k  = { ob1[p - 1].x, ob1[p - 1].y };
            df2 b2jk = { ob2[p - 1].x, ob2[p - 1].y };
            df2 b3   = { ob3[p - 1].x, ob3[p - 1].y };
            df2 a1i  = { s1h[cur][i],         s1l[cur][i] };
            df2 a2ij = { s2h[cur][i * 9 + j], s2l[cur][i * 9 + j] };
            c3 = df_add2(c3, b3);
            c3 = df_fmaf2(c3, a1i, b2jk);
            c3 = df_fmaf2(c3, a2ij, b1k);
            if (t < 81) {
                df2 a1s = { s1h[cur][t / 9], s1l[cur][t / 9] };
                df2 c2  = { s2h[cur][t],     s2l[cur][t] };
                c2 = df_add2(c2, b2jk);
                c2 = df_fmaf2(c2, a1s, b1k);
                s2h[cur ^ 1][t] = c2.hi;  s2l[cur ^ 1][t] = c2.lo;
            }
            if (t < 9) {
                df2 c1 = { s1h[cur][t], s1l[cur][t] };
                c1 = df_add2(c1, b1k);
                s1h[cur ^ 1][t] = c1.hi;  s1l[cur ^ 1][t] = c1.lo;
            }
        }
        __syncthreads();
        cur ^= 1;
    }

    float2 pb1[NB2], pb2[NB2], pb3[NB2];
    if (act) {
        #pragma unroll
        for (int q = 0; q < NB2; ++q) {
            const float2* B = sub + (long)(NB1 + 1 + q) * SIGLEN;
            pb1[q] = B[k];
            pb2[q] = B[9 + j * 9 + k];
            pb3[q] = B[90 + t];
        }
    }
    #pragma unroll
    for (int q = 0; q < NB2; ++q) {
        if (act) {
            df2 b1k  = { pb1[q].x, pb1[q].y };
            df2 b2jk = { pb2[q].x, pb2[q].y };
            df2 b3   = { pb3[q].x, pb3[q].y };
            df2 a1i  = { s1h[cur][i],         s1l[cur][i] };
            df2 a2ij = { s2h[cur][i * 9 + j], s2l[cur][i * 9 + j] };
            c3 = df_add2(c3, b3);
            c3 = df_fmaf2(c3, a1i, b2jk);
            c3 = df_fmaf2(c3, a2ij, b1k);
            if (t < 81) {
                df2 a1s = { s1h[cur][t / 9], s1l[cur][t / 9] };
                df2 c2  = { s2h[cur][t],     s2l[cur][t] };
                c2 = df_add2(c2, b2jk);
                c2 = df_fmaf2(c2, a1s, b1k);
                s2h[cur ^ 1][t] = c2.hi;  s2l[cur ^ 1][t] = c2.lo;
            }
            if (t < 9) {
                df2 c1 = { s1h[cur][t], s1l[cur][t] };
                c1 = df_add2(c1, b1k);
                s1h[cur ^ 1][t] = c1.hi;  s1l[cur ^ 1][t] = c1.lo;
            }
        }
        __syncthreads();
        cur ^= 1;
    }

    // ---- log3 (fp64, one shot) -> flat (fp32, global) ----
    float* flat = g_flat + (long)b * SIGLEN;
    if (act) {
        double s1i = (double)s1h[cur][i] + (double)s1l[cur][i];
        double s1j = (double)s1h[cur][j] + (double)s1l[cur][j];
        double s1k = (double)s1h[cur][k] + (double)s1l[cur][k];
        double s2jk = (double)s2h[cur][j * 9 + k] + (double)s2l[cur][j * 9 + k];
        double s2ij = (double)s2h[cur][i * 9 + j] + (double)s2l[cur][i * 9 + j];
        double c3d  = (double)c3.hi + (double)c3.lo;
        double l3 = c3d - 0.5 * (s1i * s2jk + s2ij * s1k) + s1i * s1j * s1k * (1.0 / 3.0);
        flat[90 + t] = (float)l3;
        if (t < 81) {
            double a = (double)s2h[cur][t] + (double)s2l[cur][t];
            double u = (double)s1h[cur][t / 9] + (double)s1l[cur][t / 9];
            double w = (double)s1h[cur][t % 9] + (double)s1l[cur][t % 9];
            flat[9 + t] = (float)(a - 0.5 * u * w);
        }
        if (t < 9) flat[t] = __fadd_rn(s1h[cur][t], s1l[cur][t]);
    }
    if (t == 0) out[b] = b2v[0];   // init for MLP atomics
}

// =====================================================================
// Launch B2: MLP, parallelized over column groups. Grid (8, BATCH),
// 256 threads. Block (cg, b): columns cg*32..cg*32+31. Each thread t:
// column jj = cg*32 + (t&31), slice = t>>5 (8 slices over m).
// h_j = relu(b1[j] + flat.W1[:,j]); out[b] += sum_j h_j*W2[j] (atomic).
// =====================================================================
__global__ __launch_bounds__(256)
void mlp_kernel(const float* __restrict__ W1, const float* __restrict__ b1v,
                const float* __restrict__ W2, float* __restrict__ out)
{
    __shared__ float flat_sh[SIGLEN];
    __shared__ float part[8][32];

    const int cg = blockIdx.x;
    const int b  = blockIdx.y;
    const int t  = threadIdx.x;
    const int jj = cg * 32 + (t & 31);
    const int slice = t >> 5;

    const float* flat = g_flat + (long)b * SIGLEN;
    for (int m = t; m < SIGLEN; m += 256) flat_sh[m] = flat[m];
    __syncthreads();

    float acc = 0.0f;
    #pragma unroll 4
    for (int m = slice; m < SIGLEN; m += 8)
        acc = fmaf(flat_sh[m], W1[(long)m * HID + jj], acc);
    part[slice][t & 31] = acc;
    __syncthreads();

    if (t < 32) {
        float h = b1v[jj];
        #pragma unroll
        for (int s = 0; s < 8; ++s) h += part[s][t];
        h = fmaxf(h, 0.0f);
        float p = h * W2[jj];
        #pragma unroll
        for (int off = 16; off > 0; off >>= 1)
            p += __shfl_down_sync(0xffffffff, p, off);
        if (t == 0) atomicAdd(out + b, p);
    }
}

// =====================================================================
extern "C" void kernel_launch(void* const* d_in, const int* in_sizes, int n_in,
                              void* d_out, int out_size)
{
    const float* x  = (const float*)d_in[0];
    const float* W1 = (const float*)d_in[1];
    const float* b1 = (const float*)d_in[2];
    const float* W2 = (const float*)d_in[3];
    const float* b2 = (const float*)d_in[4];

    sig_partial_kernel<<<dim3(GRANGES, BATCH), 96>>>(x);
    combine_kernel<<<dim3(SUBT, BATCH), 768>>>();
    finalfold_kernel<<<BATCH, 768>>>(b2, (float*)d_out);
    mlp_kernel<<<dim3(8, BATCH), 256>>>(W1, b1, W2, (float*)d_out);
}

// round 15
// speedup vs baseline: 1.0041x; 1.0041x over previous
#include <cuda_runtime.h>
#include <cstdint>

// ---------------- problem constants ----------------
#define BATCH    16
#define TSEQ     16384
#define CIN      8
#define GRANGES  256         // ranges per batch
#define LSTEPS   64          // TSEQ / GRANGES, multiple of CHUNK=32
#define SIGLEN   819         // 9 + 81 + 729
#define HID      256
#define SUBT     16          // subtrees per batch
#define RPS      16          // ranges per subtree (RPS*SUBT == GRANGES)
#define TSTRIDE  68          // channel-major row stride (floats)

// ---------------- scratch (no allocations allowed) ----------------
__device__ float  g_part[BATCH * GRANGES * SIGLEN];     // fp32 range signatures
__device__ float2 g_sub [BATCH * SUBT    * SIGLEN];     // df64 subtree signatures
__device__ float  g_flat[BATCH * SIGLEN];               // log-signature features

// ---------------- float-float (df64) helpers --------------------------
struct df2 { float hi, lo; };

__device__ __forceinline__ df2 df_add2(df2 a, df2 b) {
    float s = __fadd_rn(a.hi, b.hi);
    float v = __fsub_rn(s, a.hi);
    float e = __fadd_rn(__fsub_rn(a.hi, __fsub_rn(s, v)), __fsub_rn(b.hi, v));
    e = __fadd_rn(e, __fadd_rn(a.lo, b.lo));
    float hi = __fadd_rn(s, e);
    float lo = __fsub_rn(e, __fsub_rn(hi, s));
    df2 r; r.hi = hi; r.lo = lo; return r;
}

__device__ __forceinline__ df2 df_fmaf2(df2 a, df2 p, df2 q) {
    // a += p*q
    float ph = __fmul_rn(p.hi, q.hi);
    float pl = __fmaf_rn(p.hi, q.hi, -ph);
    pl = __fmaf_rn(p.hi, q.lo, pl);
    pl = __fmaf_rn(p.lo, q.hi, pl);
    df2 t; t.hi = ph; t.lo = pl;
    df2 r = df_add2(a, t);
    return r;
}

// =====================================================================
// Kernel 1: per-range truncated signature (levels 1..3), fp32.
// (identical to R11..R14 — 27.1/27.5 us measured)
// =====================================================================
__global__ __launch_bounds__(96)
void sig_partial_kernel(const float* __restrict__ x)
{
    __shared__ __align__(16) float ds [LSTEPS * 8];
    __shared__ __align__(16) float dst[8 * TSTRIDE];

    const int b = blockIdx.y;
    const int g = blockIdx.x;
    const int tid = threadIdx.x;
    const float DT = 1.0f / 32.0f;

    const long base = ((long)b * TSEQ + (long)g * LSTEPS) * CIN;
    for (int idx = tid; idx < LSTEPS * 8; idx += 96) {
        int s = idx >> 3, c = idx & 7;
        float cur  = x[base + idx];
        float prev = (s & 31) ? x[base + idx - 8] : 0.0f;
        ds[idx] = cur - prev;
        dst[c * TSTRIDE + s] = cur - prev;
    }
    __syncthreads();

    if (tid < 81) {
        const int i = tid / 9;
        const int j = tid % 9;
        float s1i = 0.0f, s2 = 0.0f;
        uint64_t s3p[4];
        #pragma unroll
        for (int k = 0; k < 4; ++k) s3p[k] = 0ull;
        float s38 = 0.0f;
        const float4 DT4 = make_float4(DT, DT, DT, DT);

        #pragma unroll 1
        for (int s0 = 0; s0 < LSTEPS; s0 += 4) {
            float4 di4 = (i < 8) ? *reinterpret_cast<const float4*>(&dst[i * TSTRIDE + s0]) : DT4;
            float4 dj4 = (j < 8) ? *reinterpret_cast<const float4*>(&dst[j * TSTRIDE + s0]) : DT4;
            const float* dp = ds + s0 * 8;

            #pragma unroll
            for (int u = 0; u < 4; ++u, dp += 8) {
                float di = (u == 0) ? di4.x : (u == 1) ? di4.y : (u == 2) ? di4.z : di4.w;
                float dj = (u == 0) ? dj4.x : (u == 1) ? dj4.y : (u == 2) ? dj4.z : dj4.w;
                const ulonglong2* q = reinterpret_cast<const ulonglong2*>(dp);
                ulonglong2 dl = q[0];
                ulonglong2 dh = q[1];

                float a = fmaf(fmaf(di, (1.0f / 3.0f), s1i), 0.5f * dj, s2);
                uint64_t ap;
                asm("mov.b64 %0, {%1, %2};" : "=l"(ap) : "f"(a), "f"(a));
                asm("fma.rn.f32x2 %0, %1, %2, %3;" : "=l"(s3p[0]) : "l"(ap), "l"(dl.x), "l"(s3p[0]));
                asm("fma.rn.f32x2 %0, %1, %2, %3;" : "=l"(s3p[1]) : "l"(ap), "l"(dl.y), "l"(s3p[1]));
                asm("fma.rn.f32x2 %0, %1, %2, %3;" : "=l"(s3p[2]) : "l"(ap), "l"(dh.x), "l"(s3p[2]));
                asm("fma.rn.f32x2 %0, %1, %2, %3;" : "=l"(s3p[3]) : "l"(ap), "l"(dh.y), "l"(s3p[3]));
                s38 = fmaf(a, DT, s38);

                s2  = fmaf(fmaf(di, 0.5f, s1i), dj, s2);
                s1i += di;
            }
        }

        float* out = g_part + (long)(b * GRANGES + g) * SIGLEN;
        if (j == 0) out[i] = s1i;
        out[9 + tid] = s2;
        float* o3 = out + 90 + tid * 9;
        #pragma unroll
        for (int k = 0; k < 4; ++k) {
            float lo, hi;
            asm("mov.b64 {%0, %1}, %2;" : "=f"(lo), "=f"(hi) : "l"(s3p[k]));
            o3[2 * k]     = lo;
            o3[2 * k + 1] = hi;
        }
        o3[8] = s38;
    }
}

// slot bases for a 16-leaf binary tree: L0:0..15, L1:16..23, L2:24..27, L3:28..29, L4:30
__device__ __forceinline__ int slot_base(int L) {
    return (L == 0) ? 0 : (L == 1) ? 16 : (L == 2) ? 24 : (L == 3) ? 28 : 30;
}

// =====================================================================
// Launch A: tree-fold 16 fp32 range sigs -> one df64 subtree sig.
// 4 levels, 1 barrier each. c3 of every intermediate product lives in
// registers (thread t owns element t of all products); levels 1+2 in
// 31 shared slots (reads level L-1, writes level L — no ping-pong).
// Product: c1=a1+b1 ; c2=a2+b2+a1(x)b1 ; c3=a3+b3+a1(x)b2+a2(x)b1
// (a = earlier/left operand).  Grid (SUBT, BATCH), 768 threads.
// =====================================================================
__global__ __launch_bounds__(768)
void combine_kernel()
{
    __shared__ float t1h[31][9],  t1l[31][9];
    __shared__ float t2h[31][81], t2l[31][81];

    const int b = blockIdx.y;
    const int sx = blockIdx.x;
    const int t = threadIdx.x;
    const bool act = t < 729;
    const int i = t / 81;
    const int j = (t / 9) % 9;
    const int k = t % 9;

    const float* base = g_part + (long)(b * GRANGES + sx * RPS) * SIGLEN;

    df2 c3[RPS];
    if (act) {
        #pragma unroll
        for (int s = 0; s < RPS; ++s) {
            c3[s].hi = base[(long)s * SIGLEN + 90 + t];
            c3[s].lo = 0.f;
        }
        if (t < 81) {
            #pragma unroll
            for (int s = 0; s < RPS; ++s) { t2h[s][t] = base[(long)s * SIGLEN + 9 + t]; t2l[s][t] = 0.f; }
        }
        if (t < 9) {
            #pragma unroll
            for (int s = 0; s < RPS; ++s) { t1h[s][t] = base[(long)s * SIGLEN + t]; t1l[s][t] = 0.f; }
        }
    }
    __syncthreads();

    #pragma unroll
    for (int L = 1; L <= 4; ++L) {
        const int P  = RPS >> L;
        const int sb = slot_base(L);
        const int sp = slot_base(L - 1);
        if (act) {
            #pragma unroll
            for (int q = 0; q < P; ++q) {
                const int ls = sp + 2 * q, rs = sp + 2 * q + 1;
                df2 a1i  = { t1h[ls][i],         t1l[ls][i] };
                df2 a2ij = { t2h[ls][i * 9 + j], t2l[ls][i * 9 + j] };
                df2 b1k  = { t1h[rs][k],         t1l[rs][k] };
                df2 b2jk = { t2h[rs][j * 9 + k], t2l[rs][j * 9 + k] };
                df2 r = df_add2(c3[2 * q], c3[2 * q + 1]);
                r = df_fmaf2(r, a1i, b2jk);
                r = df_fmaf2(r, a2ij, b1k);
                c3[q] = r;
            }
            if (t < 81) {
                #pragma unroll
                for (int q = 0; q < P; ++q) {
                    const int ls = sp + 2 * q, rs = sp + 2 * q + 1, dsl = sb + q;
                    df2 a2 = { t2h[ls][t],     t2l[ls][t] };
                    df2 b2 = { t2h[rs][t],     t2l[rs][t] };
                    df2 a1 = { t1h[ls][t / 9], t1l[ls][t / 9] };
                    df2 b1 = { t1h[rs][t % 9], t1l[rs][t % 9] };
                    df2 r = df_add2(a2, b2);
                    r = df_fmaf2(r, a1, b1);
                    t2h[dsl][t] = r.hi;  t2l[dsl][t] = r.lo;
                }
            }
            if (t < 9) {
                #pragma unroll
                for (int q = 0; q < P; ++q) {
                    const int ls = sp + 2 * q, rs = sp + 2 * q + 1, dsl = sb + q;
                    df2 a1 = { t1h[ls][t], t1l[ls][t] };
                    df2 b1 = { t1h[rs][t], t1l[rs][t] };
                    df2 r = df_add2(a1, b1);
                    t1h[dsl][t] = r.hi;  t1l[dsl][t] = r.lo;
                }
            }
        }
        __syncthreads();
    }

    float2* out = g_sub + (long)(b * SUBT + sx) * SIGLEN;
    if (act) {
        out[90 + t] = make_float2(c3[0].hi, c3[0].lo);
        if (t < 81) out[9 + t] = make_float2(t2h[30][t], t2l[30][t]);
        if (t < 9)  out[t]     = make_float2(t1h[30][t], t1l[30][t]);
    }
}

// =====================================================================
// Launch B1: tree-fold 16 df64 subtree sigs (same 4-level structure),
// fp64 log3, write flat; init out[b]=b2. Grid BATCH, 768 threads.
// =====================================================================
__global__ __launch_bounds__(768)
void finalfold_kernel(const float* __restrict__ b2v, float* __restrict__ out)
{
    __shared__ float t1h[31][9],  t1l[31][9];
    __shared__ float t2h[31][81], t2l[31][81];

    const int b = blockIdx.x;
    const int t = threadIdx.x;
    const bool act = t < 729;
    const int i = t / 81;
    const int j = (t / 9) % 9;
    const int k = t % 9;

    const float2* sub = g_sub + (long)(b * SUBT) * SIGLEN;

    df2 c3[SUBT];
    if (act) {
        #pragma unroll
        for (int s = 0; s < SUBT; ++s) {
            float2 v = sub[(long)s * SIGLEN + 90 + t];
            c3[s].hi = v.x; c3[s].lo = v.y;
        }
        if (t < 81) {
            #pragma unroll
            for (int s = 0; s < SUBT; ++s) { float2 v = sub[(long)s * SIGLEN + 9 + t]; t2h[s][t] = v.x; t2l[s][t] = v.y; }
        }
        if (t < 9) {
            #pragma unroll
            for (int s = 0; s < SUBT; ++s) { float2 v = sub[(long)s * SIGLEN + t]; t1h[s][t] = v.x; t1l[s][t] = v.y; }
        }
    }
    __syncthreads();

    #pragma unroll
    for (int L = 1; L <= 4; ++L) {
        const int P  = SUBT >> L;
        const int sb = slot_base(L);
        const int sp = slot_base(L - 1);
        if (act) {
            #pragma unroll
            for (int q = 0; q < P; ++q) {
                const int ls = sp + 2 * q, rs = sp + 2 * q + 1;
                df2 a1i  = { t1h[ls][i],         t1l[ls][i] };
                df2 a2ij = { t2h[ls][i * 9 + j], t2l[ls][i * 9 + j] };
                df2 b1k  = { t1h[rs][k],         t1l[rs][k] };
                df2 b2jk = { t2h[rs][j * 9 + k], t2l[rs][j * 9 + k] };
                df2 r = df_add2(c3[2 * q], c3[2 * q + 1]);
                r = df_fmaf2(r, a1i, b2jk);
                r = df_fmaf2(r, a2ij, b1k);
                c3[q] = r;
            }
            if (t < 81) {
                #pragma unroll
                for (int q = 0; q < P; ++q) {
                    const int ls = sp + 2 * q, rs = sp + 2 * q + 1, dsl = sb + q;
                    df2 a2 = { t2h[ls][t],     t2l[ls][t] };
                    df2 b2 = { t2h[rs][t],     t2l[rs][t] };
                    df2 a1 = { t1h[ls][t / 9], t1l[ls][t / 9] };
                    df2 b1 = { t1h[rs][t % 9], t1l[rs][t % 9] };
                    df2 r = df_add2(a2, b2);
                    r = df_fmaf2(r, a1, b1);
                    t2h[dsl][t] = r.hi;  t2l[dsl][t] = r.lo;
                }
            }
            if (t < 9) {
                #pragma unroll
                for (int q = 0; q < P; ++q) {
                    const int ls = sp + 2 * q, rs = sp + 2 * q + 1, dsl = sb + q;
                    df2 a1 = { t1h[ls][t], t1l[ls][t] };
                    df2 b1 = { t1h[rs][t], t1l[rs][t] };
                    df2 r = df_add2(a1, b1);
                    t1h[dsl][t] = r.hi;  t1l[dsl][t] = r.lo;
                }
            }
        }
        __syncthreads();
    }

    // ---- log3 (fp64, one shot) -> flat (fp32, global) ----
    float* flat = g_flat + (long)b * SIGLEN;
    if (act) {
        double s1i = (double)t1h[30][i] + (double)t1l[30][i];
        double s1j = (double)t1h[30][j] + (double)t1l[30][j];
        double s1k = (double)t1h[30][k] + (double)t1l[30][k];
        double s2jk = (double)t2h[30][j * 9 + k] + (double)t2l[30][j * 9 + k];
        double s2ij = (double)t2h[30][i * 9 + j] + (double)t2l[30][i * 9 + j];
        double c3d  = (double)c3[0].hi + (double)c3[0].lo;
        double l3 = c3d - 0.5 * (s1i * s2jk + s2ij * s1k) + s1i * s1j * s1k * (1.0 / 3.0);
        flat[90 + t] = (float)l3;
        if (t < 81) {
            double a = (double)t2h[30][t] + (double)t2l[30][t];
            double u = (double)t1h[30][t / 9] + (double)t1l[30][t / 9];
            double w = (double)t1h[30][t % 9] + (double)t1l[30][t % 9];
            flat[9 + t] = (float)(a - 0.5 * u * w);
        }
        if (t < 9) flat[t] = __fadd_rn(t1h[30][t], t1l[30][t]);
    }
    if (t == 0) out[b] = b2v[0];   // init for MLP atomics
}

// =====================================================================
// Launch B2: MLP over column groups. Grid (8, BATCH), 256 threads.
// 8 independent accumulators -> 8 loads in flight per thread.
// =====================================================================
__global__ __launch_bounds__(256)
void mlp_kernel(const float* __restrict__ W1, const float* __restrict__ b1v,
                const float* __restrict__ W2, float* __restrict__ out)
{
    __shared__ float flat_sh[SIGLEN];
    __shared__ float part[8][32];

    const int cg = blockIdx.x;
    const int b  = blockIdx.y;
    const int t  = threadIdx.x;
    const int jj = cg * 32 + (t & 31);
    const int slice = t >> 5;

    const float* flat = g_flat + (long)b * SIGLEN;
    for (int m = t; m < SIGLEN; m += 256) flat_sh[m] = flat[m];
    __syncthreads();

    float acc[8];
    #pragma unroll
    for (int u = 0; u < 8; ++u) acc[u] = 0.0f;

    #pragma unroll 1
    for (int m0 = slice; m0 < SIGLEN; m0 += 64) {
        #pragma unroll
        for (int u = 0; u < 8; ++u) {
            int m = m0 + u * 8;
            if (m < SIGLEN)
                acc[u] = fmaf(flat_sh[m], W1[(long)m * HID + jj], acc[u]);
        }
    }
    float a01 = acc[0] + acc[1], a23 = acc[2] + acc[3];
    float a45 = acc[4] + acc[5], a67 = acc[6] + acc[7];
    part[slice][t & 31] = (a01 + a23) + (a45 + a67);
    __syncthreads();

    if (t < 32) {
        float h = b1v[jj];
        #pragma unroll
        for (int s = 0; s < 8; ++s) h += part[s][t];
        h = fmaxf(h, 0.0f);
        float p = h * W2[jj];
        #pragma unroll
        for (int off = 16; off > 0; off >>= 1)
            p += __shfl_down_sync(0xffffffff, p, off);
        if (t == 0) atomicAdd(out + b, p);
    }
}

// =====================================================================
extern "C" void kernel_launch(void* const* d_in, const int* in_sizes, int n_in,
                              void* d_out, int out_size)
{
    const float* x  = (const float*)d_in[0];
    const float* W1 = (const float*)d_in[1];
    const float* b1 = (const float*)d_in[2];
    const float* W2 = (const float*)d_in[3];
    const float* b2 = (const float*)d_in[4];

    sig_partial_kernel<<<dim3(GRANGES, BATCH), 96>>>(x);
    combine_kernel<<<dim3(SUBT, BATCH), 768>>>();
    finalfold_kernel<<<BATCH, 768>>>(b2, (float*)d_out);
    mlp_kernel<<<dim3(8, BATCH), 256>>>(W1, b1, W2, (float*)d_out);
}